// round 1
// baseline (speedup 1.0000x reference)
#include <cuda_runtime.h>
#include <cuda_bf16.h>
#include <cstdint>

// ChamferLoss: B=128, N=M=1024, 3D points stored as float4 (channel 0 unused).
// Strategy: both directions as independent row-parallel min-reductions.
// dist_sq(n,m) = pn[n] + qn[m] - 2*dot(p3[n], q3[m]); pn constant along the
// min axis, so per pair we only track min(qn[m] - 2*dot). Packed f32x2 FMA
// processes two column points per instruction.

#define BATCHES   128
#define NPTS      1024
#define THREADS   128
#define CHUNKS    4            // row chunks per (batch, direction)
#define ROWS_PER_CHUNK (NPTS / CHUNKS)   // 256
#define ROWS_PER_THREAD (ROWS_PER_CHUNK / THREADS) // 2
#define NGROUPS   (NPTS / 2)   // 512 packed column-point pairs

__device__ __forceinline__ unsigned long long pack2(float a, float b) {
    unsigned long long r;
    asm("mov.b64 %0, {%1, %2};" : "=l"(r) : "f"(a), "f"(b));
    return r;
}
__device__ __forceinline__ void unpack2(unsigned long long v, float& a, float& b) {
    asm("mov.b64 {%0, %1}, %2;" : "=f"(a), "=f"(b) : "l"(v));
}
__device__ __forceinline__ unsigned long long mul2(unsigned long long a, unsigned long long b) {
    unsigned long long d;
    asm("mul.rn.f32x2 %0, %1, %2;" : "=l"(d) : "l"(a), "l"(b));
    return d;
}
__device__ __forceinline__ unsigned long long fma2(unsigned long long a, unsigned long long b,
                                                   unsigned long long c) {
    unsigned long long d;
    asm("fma.rn.f32x2 %0, %1, %2, %3;" : "=l"(d) : "l"(a), "l"(b), "l"(c));
    return d;
}

__global__ void __launch_bounds__(THREADS)
chamfer_zero_kernel(float* out) {
    if (threadIdx.x == 0) out[0] = 0.0f;
}

__global__ void __launch_bounds__(THREADS)
chamfer_main_kernel(const float4* __restrict__ p, const float4* __restrict__ q,
                    float* __restrict__ out) {
    // Packed column data: group j holds points (2j, 2j+1):
    //   sq[4j+0] = (y0,y1)  sq[4j+1] = (z0,z1)  sq[4j+2] = (w0,w1)  sq[4j+3] = (n0,n1)
    __shared__ unsigned long long sq[NGROUPS * 4];
    __shared__ float warp_sums[THREADS / 32];

    const int bid   = blockIdx.x;
    const int chunk = bid & (CHUNKS - 1);
    const int bd    = bid >> 2;
    const int dir   = bd & 1;
    const int b     = bd >> 1;
    const int tid   = threadIdx.x;

    const float4* rowpts = (dir == 0) ? (p + b * NPTS) : (q + b * NPTS);
    const float4* colpts = (dir == 0) ? (q + b * NPTS) : (p + b * NPTS);

    // ---- Fill packed column smem (each thread handles 4 point-pairs) ----
    #pragma unroll
    for (int i = tid; i < NGROUPS; i += THREADS) {
        float4 P0 = colpts[2 * i];
        float4 P1 = colpts[2 * i + 1];
        float n0 = P0.y * P0.y + P0.z * P0.z + P0.w * P0.w;
        float n1 = P1.y * P1.y + P1.z * P1.z + P1.w * P1.w;
        sq[4 * i + 0] = pack2(P0.y, P1.y);
        sq[4 * i + 1] = pack2(P0.z, P1.z);
        sq[4 * i + 2] = pack2(P0.w, P1.w);
        sq[4 * i + 3] = pack2(n0, n1);
    }

    // ---- Load this thread's 2 row points ----
    const int r0 = chunk * ROWS_PER_CHUNK + tid;
    const int r1 = r0 + THREADS;
    float4 RP0 = rowpts[r0];
    float4 RP1 = rowpts[r1];

    const unsigned long long px0 = pack2(RP0.y, RP0.y);
    const unsigned long long py0 = pack2(RP0.z, RP0.z);
    const unsigned long long pz0 = pack2(RP0.w, RP0.w);
    const unsigned long long px1 = pack2(RP1.y, RP1.y);
    const unsigned long long py1 = pack2(RP1.z, RP1.z);
    const unsigned long long pz1 = pack2(RP1.w, RP1.w);
    const unsigned long long NEG2 = pack2(-2.0f, -2.0f);

    const float pn0 = RP0.y * RP0.y + RP0.z * RP0.z + RP0.w * RP0.w;
    const float pn1 = RP1.y * RP1.y + RP1.z * RP1.z + RP1.w * RP1.w;

    __syncthreads();

    float m0a = 3.4e38f, m0b = 3.4e38f;   // row 0 partial mins (even/odd m)
    float m1a = 3.4e38f, m1b = 3.4e38f;   // row 1

    const ulonglong2* sq2 = (const ulonglong2*)sq;

    #pragma unroll 8
    for (int j = 0; j < NGROUPS; j++) {
        ulonglong2 u01 = sq2[2 * j];       // (yy, zz)
        ulonglong2 u23 = sq2[2 * j + 1];   // (ww, nn)

        // row 0: t = nn - 2 * dot(p0, col)
        unsigned long long s0 = mul2(px0, u01.x);
        s0 = fma2(py0, u01.y, s0);
        s0 = fma2(pz0, u23.x, s0);
        s0 = fma2(s0, NEG2, u23.y);
        float t0, t1;
        unpack2(s0, t0, t1);
        m0a = fminf(m0a, t0);
        m0b = fminf(m0b, t1);

        // row 1
        unsigned long long s1 = mul2(px1, u01.x);
        s1 = fma2(py1, u01.y, s1);
        s1 = fma2(pz1, u23.x, s1);
        s1 = fma2(s1, NEG2, u23.y);
        float v0, v1;
        unpack2(s1, v0, v1);
        m1a = fminf(m1a, v0);
        m1b = fminf(m1b, v1);
    }

    float ds0 = pn0 + fminf(m0a, m0b);
    float ds1 = pn1 + fminf(m1a, m1b);
    float d0 = sqrtf(fmaxf(ds0, 0.0f) + 1e-16f);
    float d1 = sqrtf(fmaxf(ds1, 0.0f) + 1e-16f);
    float local = d0 + d1;

    // ---- Block reduction ----
    #pragma unroll
    for (int off = 16; off > 0; off >>= 1)
        local += __shfl_xor_sync(0xFFFFFFFFu, local, off);

    const int wid = tid >> 5;
    const int lid = tid & 31;
    if (lid == 0) warp_sums[wid] = local;
    __syncthreads();

    if (wid == 0) {
        float s = (lid < (THREADS / 32)) ? warp_sums[lid] : 0.0f;
        #pragma unroll
        for (int off = 2; off > 0; off >>= 1)
            s += __shfl_xor_sync(0xFFFFFFFFu, s, off);
        if (lid == 0) atomicAdd(out, 0.5f * s);
    }
}

extern "C" void kernel_launch(void* const* d_in, const int* in_sizes, int n_in,
                              void* d_out, int out_size) {
    const float4* p = (const float4*)d_in[0];
    const float4* q = (const float4*)d_in[1];
    float* out = (float*)d_out;

    chamfer_zero_kernel<<<1, THREADS>>>(out);
    chamfer_main_kernel<<<BATCHES * 2 * CHUNKS, THREADS>>>(p, q, out);
}

// round 2
// speedup vs baseline: 1.0768x; 1.0768x over previous
#include <cuda_runtime.h>
#include <cuda_bf16.h>
#include <cstdint>

// ChamferLoss: B=128, N=M=1024, 3D points stored as float4 (channel 0 unused).
// dist_sq(n,m) = pn[n] + (qn[m] - 2*dot(p3[n], q3[m])); pn constant along the
// min axis. Pre-scale row coords by -2 so each 2-column evaluation is exactly
// 3 packed f32x2 FMAs. 4 rows/thread amortizes the 2 LDS.128 per column group.

#define BATCHES   128
#define NPTS      1024
#define THREADS   64
#define CHUNKS    4
#define RPT       4            // rows per thread
#define ROWS_PER_CHUNK (NPTS / CHUNKS)            // 256 = THREADS * RPT
#define NGROUPS   (NPTS / 2)   // 512 packed column-point pairs

__device__ __forceinline__ unsigned long long pack2(float a, float b) {
    unsigned long long r;
    asm("mov.b64 %0, {%1, %2};" : "=l"(r) : "f"(a), "f"(b));
    return r;
}
__device__ __forceinline__ void unpack2(unsigned long long v, float& a, float& b) {
    asm("mov.b64 {%0, %1}, %2;" : "=f"(a), "=f"(b) : "l"(v));
}
__device__ __forceinline__ unsigned long long fma2(unsigned long long a, unsigned long long b,
                                                   unsigned long long c) {
    unsigned long long d;
    asm("fma.rn.f32x2 %0, %1, %2, %3;" : "=l"(d) : "l"(a), "l"(b), "l"(c));
    return d;
}

__global__ void __launch_bounds__(THREADS)
chamfer_zero_kernel(float* out) {
    if (threadIdx.x == 0) out[0] = 0.0f;
}

__global__ void __launch_bounds__(THREADS)
chamfer_main_kernel(const float4* __restrict__ p, const float4* __restrict__ q,
                    float* __restrict__ out) {
    // Packed column data: group j holds points (2j, 2j+1):
    //   sq[4j+0] = (y0,y1)  sq[4j+1] = (z0,z1)  sq[4j+2] = (w0,w1)  sq[4j+3] = (n0,n1)
    __shared__ unsigned long long sq[NGROUPS * 4];
    __shared__ float warp_sums[THREADS / 32];

    const int bid   = blockIdx.x;
    const int chunk = bid & (CHUNKS - 1);
    const int bd    = bid >> 2;
    const int dir   = bd & 1;
    const int b     = bd >> 1;
    const int tid   = threadIdx.x;

    const float4* rowpts = (dir == 0) ? (p + b * NPTS) : (q + b * NPTS);
    const float4* colpts = (dir == 0) ? (q + b * NPTS) : (p + b * NPTS);

    // ---- Fill packed column smem ----
    #pragma unroll
    for (int i = tid; i < NGROUPS; i += THREADS) {
        float4 P0 = colpts[2 * i];
        float4 P1 = colpts[2 * i + 1];
        float n0 = P0.y * P0.y + P0.z * P0.z + P0.w * P0.w;
        float n1 = P1.y * P1.y + P1.z * P1.z + P1.w * P1.w;
        sq[4 * i + 0] = pack2(P0.y, P1.y);
        sq[4 * i + 1] = pack2(P0.z, P1.z);
        sq[4 * i + 2] = pack2(P0.w, P1.w);
        sq[4 * i + 3] = pack2(n0, n1);
    }

    // ---- Load this thread's RPT row points, pre-scale by -2 ----
    unsigned long long cx[RPT], cy[RPT], cz[RPT];
    float pn[RPT];
    #pragma unroll
    for (int k = 0; k < RPT; k++) {
        int r = chunk * ROWS_PER_CHUNK + k * THREADS + tid;
        float4 RP = rowpts[r];
        pn[k] = RP.y * RP.y + RP.z * RP.z + RP.w * RP.w;
        float ax = -2.0f * RP.y, ay = -2.0f * RP.z, az = -2.0f * RP.w;
        cx[k] = pack2(ax, ax);
        cy[k] = pack2(ay, ay);
        cz[k] = pack2(az, az);
    }

    __syncthreads();

    float ma[RPT], mb[RPT];
    #pragma unroll
    for (int k = 0; k < RPT; k++) { ma[k] = 3.4e38f; mb[k] = 3.4e38f; }

    const ulonglong2* sq2 = (const ulonglong2*)sq;

    #pragma unroll 4
    for (int j = 0; j < NGROUPS; j++) {
        ulonglong2 u01 = sq2[2 * j];       // (yy, zz)
        ulonglong2 u23 = sq2[2 * j + 1];   // (ww, nn)
        #pragma unroll
        for (int k = 0; k < RPT; k++) {
            unsigned long long s = fma2(cx[k], u01.x, u23.y);  // -2px*x + n
            s = fma2(cy[k], u01.y, s);
            s = fma2(cz[k], u23.x, s);
            float t0, t1;
            unpack2(s, t0, t1);
            ma[k] = fminf(ma[k], t0);
            mb[k] = fminf(mb[k], t1);
        }
    }

    float local = 0.0f;
    #pragma unroll
    for (int k = 0; k < RPT; k++) {
        float ds = pn[k] + fminf(ma[k], mb[k]);
        local += sqrtf(fmaxf(ds, 0.0f) + 1e-16f);
    }

    // ---- Block reduction (2 warps) ----
    #pragma unroll
    for (int off = 16; off > 0; off >>= 1)
        local += __shfl_xor_sync(0xFFFFFFFFu, local, off);

    const int wid = tid >> 5;
    const int lid = tid & 31;
    if (lid == 0) warp_sums[wid] = local;
    __syncthreads();

    if (tid == 0) {
        float s = warp_sums[0] + warp_sums[1];
        atomicAdd(out, 0.5f * s);
    }
}

extern "C" void kernel_launch(void* const* d_in, const int* in_sizes, int n_in,
                              void* d_out, int out_size) {
    const float4* p = (const float4*)d_in[0];
    const float4* q = (const float4*)d_in[1];
    float* out = (float*)d_out;

    chamfer_zero_kernel<<<1, THREADS>>>(out);
    chamfer_main_kernel<<<BATCHES * 2 * CHUNKS, THREADS>>>(p, q, out);
}

// round 3
// speedup vs baseline: 1.1612x; 1.0783x over previous
#include <cuda_runtime.h>
#include <cuda_bf16.h>
#include <cstdint>

// ChamferLoss: B=128, N=M=1024, 3D points stored as float4 (channel 0 unused).
// dist_sq(n,m) = pn[n] + (qn[m] - 2*dot(p3[n], q3[m])); pn constant along the
// min axis. Row coords pre-scaled by -2: each 2-column eval = 3 packed f32x2
// FMAs. 4 rows/thread amortizes 2 LDS.128 per column group. Inner loop is
// explicitly software-pipelined (1-deep smem prefetch) to hide LDS latency.

#define BATCHES   128
#define NPTS      1024
#define THREADS   64
#define CHUNKS    4
#define RPT       4            // rows per thread
#define ROWS_PER_CHUNK (NPTS / CHUNKS)            // 256 = THREADS * RPT
#define NGROUPS   (NPTS / 2)   // 512 packed column-point pairs

__device__ __forceinline__ unsigned long long pack2(float a, float b) {
    unsigned long long r;
    asm("mov.b64 %0, {%1, %2};" : "=l"(r) : "f"(a), "f"(b));
    return r;
}
__device__ __forceinline__ void unpack2(unsigned long long v, float& a, float& b) {
    asm("mov.b64 {%0, %1}, %2;" : "=f"(a), "=f"(b) : "l"(v));
}
__device__ __forceinline__ unsigned long long fma2(unsigned long long a, unsigned long long b,
                                                   unsigned long long c) {
    unsigned long long d;
    asm("fma.rn.f32x2 %0, %1, %2, %3;" : "=l"(d) : "l"(a), "l"(b), "l"(c));
    return d;
}

__global__ void __launch_bounds__(THREADS)
chamfer_zero_kernel(float* out) {
    if (threadIdx.x == 0) out[0] = 0.0f;
}

__global__ void __launch_bounds__(THREADS, 8)
chamfer_main_kernel(const float4* __restrict__ p, const float4* __restrict__ q,
                    float* __restrict__ out) {
    // Packed column data: group j holds points (2j, 2j+1):
    //   sq[4j+0] = (y0,y1)  sq[4j+1] = (z0,z1)  sq[4j+2] = (w0,w1)  sq[4j+3] = (n0,n1)
    // One extra padding group so the prefetch of j+1 never goes OOB.
    __shared__ unsigned long long sq[(NGROUPS + 1) * 4];
    __shared__ float warp_sums[THREADS / 32];

    const int bid   = blockIdx.x;
    const int chunk = bid & (CHUNKS - 1);
    const int bd    = bid >> 2;
    const int dir   = bd & 1;
    const int b     = bd >> 1;
    const int tid   = threadIdx.x;

    const float4* rowpts = (dir == 0) ? (p + b * NPTS) : (q + b * NPTS);
    const float4* colpts = (dir == 0) ? (q + b * NPTS) : (p + b * NPTS);

    // ---- Fill packed column smem ----
    #pragma unroll
    for (int i = tid; i < NGROUPS; i += THREADS) {
        float4 P0 = colpts[2 * i];
        float4 P1 = colpts[2 * i + 1];
        float n0 = P0.y * P0.y + P0.z * P0.z + P0.w * P0.w;
        float n1 = P1.y * P1.y + P1.z * P1.z + P1.w * P1.w;
        sq[4 * i + 0] = pack2(P0.y, P1.y);
        sq[4 * i + 1] = pack2(P0.z, P1.z);
        sq[4 * i + 2] = pack2(P0.w, P1.w);
        sq[4 * i + 3] = pack2(n0, n1);
    }
    if (tid < 4) sq[4 * NGROUPS + tid] = 0;   // padding group (values unused)

    // ---- Load this thread's RPT row points, pre-scale by -2 ----
    unsigned long long cx[RPT], cy[RPT], cz[RPT];
    float pn[RPT];
    #pragma unroll
    for (int k = 0; k < RPT; k++) {
        int r = chunk * ROWS_PER_CHUNK + k * THREADS + tid;
        float4 RP = rowpts[r];
        pn[k] = RP.y * RP.y + RP.z * RP.z + RP.w * RP.w;
        float ax = -2.0f * RP.y, ay = -2.0f * RP.z, az = -2.0f * RP.w;
        cx[k] = pack2(ax, ax);
        cy[k] = pack2(ay, ay);
        cz[k] = pack2(az, az);
    }

    __syncthreads();

    float ma[RPT], mb[RPT];
    #pragma unroll
    for (int k = 0; k < RPT; k++) { ma[k] = 3.4e38f; mb[k] = 3.4e38f; }

    const ulonglong2* sq2 = (const ulonglong2*)sq;

    // ---- Software-pipelined main loop: prefetch group j+1 while computing j ----
    ulonglong2 u01 = sq2[0];     // (yy, zz)
    ulonglong2 u23 = sq2[1];     // (ww, nn)

    #pragma unroll 8
    for (int j = 0; j < NGROUPS; j++) {
        ulonglong2 n01 = sq2[2 * (j + 1)];
        ulonglong2 n23 = sq2[2 * (j + 1) + 1];

        #pragma unroll
        for (int k = 0; k < RPT; k++) {
            unsigned long long s = fma2(cx[k], u01.x, u23.y);  // -2px*x + n
            s = fma2(cy[k], u01.y, s);
            s = fma2(cz[k], u23.x, s);
            float t0, t1;
            unpack2(s, t0, t1);
            ma[k] = fminf(ma[k], t0);
            mb[k] = fminf(mb[k], t1);
        }

        u01 = n01;
        u23 = n23;
    }

    float local = 0.0f;
    #pragma unroll
    for (int k = 0; k < RPT; k++) {
        float ds = pn[k] + fminf(ma[k], mb[k]);
        local += sqrtf(fmaxf(ds, 0.0f) + 1e-16f);
    }

    // ---- Block reduction (2 warps) ----
    #pragma unroll
    for (int off = 16; off > 0; off >>= 1)
        local += __shfl_xor_sync(0xFFFFFFFFu, local, off);

    const int wid = tid >> 5;
    const int lid = tid & 31;
    if (lid == 0) warp_sums[wid] = local;
    __syncthreads();

    if (tid == 0) {
        float s = warp_sums[0] + warp_sums[1];
        atomicAdd(out, 0.5f * s);
    }
}

extern "C" void kernel_launch(void* const* d_in, const int* in_sizes, int n_in,
                              void* d_out, int out_size) {
    const float4* p = (const float4*)d_in[0];
    const float4* q = (const float4*)d_in[1];
    float* out = (float*)d_out;

    chamfer_zero_kernel<<<1, THREADS>>>(out);
    chamfer_main_kernel<<<BATCHES * 2 * CHUNKS, THREADS>>>(p, q, out);
}

// round 4
// speedup vs baseline: 1.1857x; 1.0212x over previous
#include <cuda_runtime.h>
#include <cuda_bf16.h>
#include <cstdint>

// ChamferLoss: B=128, N=M=1024, 3D points stored as float4 (channel 0 unused).
// dist_sq(n,m) = pn[n] + (qn[m] - 2*dot(p3[n], q3[m])); pn constant along the
// min axis. Row coords pre-scaled by -2: each 2-column eval = 3 packed f32x2
// FMAs. RPT=2 rows/thread with 128-thread blocks doubles resident warps
// (6.9/SMSP) to cover f32x2 register-bank rt=3 issue bubbles.

#define BATCHES   128
#define NPTS      1024
#define THREADS   128
#define CHUNKS    4
#define RPT       2            // rows per thread
#define ROWS_PER_CHUNK (NPTS / CHUNKS)            // 256 = THREADS * RPT
#define NGROUPS   (NPTS / 2)   // 512 packed column-point pairs

__device__ __forceinline__ unsigned long long pack2(float a, float b) {
    unsigned long long r;
    asm("mov.b64 %0, {%1, %2};" : "=l"(r) : "f"(a), "f"(b));
    return r;
}
__device__ __forceinline__ void unpack2(unsigned long long v, float& a, float& b) {
    asm("mov.b64 {%0, %1}, %2;" : "=f"(a), "=f"(b) : "l"(v));
}
__device__ __forceinline__ unsigned long long fma2(unsigned long long a, unsigned long long b,
                                                   unsigned long long c) {
    unsigned long long d;
    asm("fma.rn.f32x2 %0, %1, %2, %3;" : "=l"(d) : "l"(a), "l"(b), "l"(c));
    return d;
}

__global__ void __launch_bounds__(THREADS)
chamfer_zero_kernel(float* out) {
    if (threadIdx.x == 0) out[0] = 0.0f;
}

__global__ void __launch_bounds__(THREADS, 8)
chamfer_main_kernel(const float4* __restrict__ p, const float4* __restrict__ q,
                    float* __restrict__ out) {
    // Packed column data: group j holds points (2j, 2j+1):
    //   sq[4j+0] = (y0,y1)  sq[4j+1] = (z0,z1)  sq[4j+2] = (w0,w1)  sq[4j+3] = (n0,n1)
    // One extra padding group so the prefetch of j+1 never goes OOB.
    __shared__ unsigned long long sq[(NGROUPS + 1) * 4];
    __shared__ float warp_sums[THREADS / 32];

    const int bid   = blockIdx.x;
    const int chunk = bid & (CHUNKS - 1);
    const int bd    = bid >> 2;
    const int dir   = bd & 1;
    const int b     = bd >> 1;
    const int tid   = threadIdx.x;

    const float4* rowpts = (dir == 0) ? (p + b * NPTS) : (q + b * NPTS);
    const float4* colpts = (dir == 0) ? (q + b * NPTS) : (p + b * NPTS);

    // ---- Fill packed column smem ----
    #pragma unroll
    for (int i = tid; i < NGROUPS; i += THREADS) {
        float4 P0 = colpts[2 * i];
        float4 P1 = colpts[2 * i + 1];
        float n0 = P0.y * P0.y + P0.z * P0.z + P0.w * P0.w;
        float n1 = P1.y * P1.y + P1.z * P1.z + P1.w * P1.w;
        sq[4 * i + 0] = pack2(P0.y, P1.y);
        sq[4 * i + 1] = pack2(P0.z, P1.z);
        sq[4 * i + 2] = pack2(P0.w, P1.w);
        sq[4 * i + 3] = pack2(n0, n1);
    }
    if (tid < 4) sq[4 * NGROUPS + tid] = 0;   // padding group (values unused)

    // ---- Load this thread's RPT row points, pre-scale by -2 ----
    unsigned long long cx[RPT], cy[RPT], cz[RPT];
    float pn[RPT];
    #pragma unroll
    for (int k = 0; k < RPT; k++) {
        int r = chunk * ROWS_PER_CHUNK + k * THREADS + tid;
        float4 RP = rowpts[r];
        pn[k] = RP.y * RP.y + RP.z * RP.z + RP.w * RP.w;
        float ax = -2.0f * RP.y, ay = -2.0f * RP.z, az = -2.0f * RP.w;
        cx[k] = pack2(ax, ax);
        cy[k] = pack2(ay, ay);
        cz[k] = pack2(az, az);
    }

    __syncthreads();

    float ma[RPT], mb[RPT];
    #pragma unroll
    for (int k = 0; k < RPT; k++) { ma[k] = 3.4e38f; mb[k] = 3.4e38f; }

    const ulonglong2* sq2 = (const ulonglong2*)sq;

    // ---- Software-pipelined main loop: prefetch group j+1 while computing j ----
    ulonglong2 u01 = sq2[0];     // (yy, zz)
    ulonglong2 u23 = sq2[1];     // (ww, nn)

    #pragma unroll 8
    for (int j = 0; j < NGROUPS; j++) {
        ulonglong2 n01 = sq2[2 * (j + 1)];
        ulonglong2 n23 = sq2[2 * (j + 1) + 1];

        #pragma unroll
        for (int k = 0; k < RPT; k++) {
            unsigned long long s = fma2(cx[k], u01.x, u23.y);  // -2px*x + n
            s = fma2(cy[k], u01.y, s);
            s = fma2(cz[k], u23.x, s);
            float t0, t1;
            unpack2(s, t0, t1);
            ma[k] = fminf(ma[k], t0);
            mb[k] = fminf(mb[k], t1);
        }

        u01 = n01;
        u23 = n23;
    }

    float local = 0.0f;
    #pragma unroll
    for (int k = 0; k < RPT; k++) {
        float ds = pn[k] + fminf(ma[k], mb[k]);
        local += sqrtf(fmaxf(ds, 0.0f) + 1e-16f);
    }

    // ---- Block reduction (4 warps) ----
    #pragma unroll
    for (int off = 16; off > 0; off >>= 1)
        local += __shfl_xor_sync(0xFFFFFFFFu, local, off);

    const int wid = tid >> 5;
    const int lid = tid & 31;
    if (lid == 0) warp_sums[wid] = local;
    __syncthreads();

    if (tid == 0) {
        float s = warp_sums[0] + warp_sums[1] + warp_sums[2] + warp_sums[3];
        atomicAdd(out, 0.5f * s);
    }
}

extern "C" void kernel_launch(void* const* d_in, const int* in_sizes, int n_in,
                              void* d_out, int out_size) {
    const float4* p = (const float4*)d_in[0];
    const float4* q = (const float4*)d_in[1];
    float* out = (float*)d_out;

    chamfer_zero_kernel<<<1, THREADS>>>(out);
    chamfer_main_kernel<<<BATCHES * 2 * CHUNKS, THREADS>>>(p, q, out);
}